// round 6
// baseline (speedup 1.0000x reference)
#include <cuda_runtime.h>
#include <cuda_bf16.h>

// TextureMartingaleModule: x[8,16,256,256] f32 -> out[8,64,256,256] f32
// Per channel, per pixel (3x3 zero-padded window):
//   contrast = (S2c/9) / (sqrt(S2c/8)+eps)^2,  S2c = sum(p^2) - s1^2/9
//   energy   = sum(p^2)/9
//   entropy  = -sum(p*log(p+eps))/9
//   homog    = 1 / (1 + sum|p - mean|/9)
//   out      = (feat + eps) * exp(-0.5)        (theta=1 collapses exp/log)

#define IMG_H 256
#define IMG_W 256
#define TW 64          // tile width (outputs)
#define TH 16          // tile height (outputs)
#define SROWS (TH + 2) // 18
#define SCOLS (TW + 2) // 66
#define SSTRIDE 67     // padded to odd for bank-conflict mitigation

__global__ __launch_bounds__(256, 4)
void texture_martingale_kernel(const float* __restrict__ x,
                               float* __restrict__ out)
{
    __shared__ float sp[SROWS][SSTRIDE];
    __shared__ float sq[SROWS][SSTRIDE];

    const int img = blockIdx.z;                  // b*C + c  (0..127)
    const int x0  = blockIdx.x * TW;
    const int y0  = blockIdx.y * TH;
    const float* __restrict__ base = x + (size_t)img * (IMG_H * IMG_W);

    const int tid = threadIdx.x;

    // ---- Fill halo tile: p and q = p*log(p+eps), zero padding outside ----
    #pragma unroll
    for (int i = tid; i < SROWS * SCOLS; i += 256) {
        int r = i / SCOLS;
        int c = i - r * SCOLS;
        int gy = y0 + r - 1;
        int gx = x0 + c - 1;
        float p = 0.0f;
        if ((unsigned)gy < (unsigned)IMG_H && (unsigned)gx < (unsigned)IMG_W)
            p = __ldg(base + gy * IMG_W + gx);
        sp[r][c] = p;
        sq[r][c] = p * __logf(p + 1e-6f);
    }
    __syncthreads();

    // ---- Each thread computes 4 x-consecutive outputs ----
    const int tx = tid & 15;          // 0..15  -> x quad
    const int ty = tid >> 4;          // 0..15  -> y row
    const int cx = tx * 4;            // smem col base (taps span cx..cx+5)

    float p[3][6];
    float c1[6], c2[6], cq[6];
    #pragma unroll
    for (int c = 0; c < 6; c++) { c1[c] = 0.f; c2[c] = 0.f; cq[c] = 0.f; }

    #pragma unroll
    for (int r = 0; r < 3; r++) {
        #pragma unroll
        for (int c = 0; c < 6; c++) {
            float v = sp[ty + r][cx + c];
            p[r][c] = v;
            c1[c] += v;
            c2[c]  = fmaf(v, v, c2[c]);
            cq[c] += sq[ty + r][cx + c];
        }
    }

    const float INV9 = 1.0f / 9.0f;
    const float ENH  = 0.60653065971263342f;  // exp(-0.5)
    const float EPS  = 1e-6f;

    float oc[4], oe[4], on[4], oh[4];

    #pragma unroll
    for (int j = 0; j < 4; j++) {
        float s1 = c1[j] + c1[j + 1] + c1[j + 2];
        float s2 = c2[j] + c2[j + 1] + c2[j + 2];
        float sl = cq[j] + cq[j + 1] + cq[j + 2];

        float m  = s1 * INV9;
        float v  = fmaxf(s2 - s1 * m, 0.0f);        // sum (p - m)^2
        float sd = sqrtf(v * 0.125f) + EPS;         // unbiased std + eps
        float contrast = __fdividef(v * INV9, sd * sd);
        float energy   = s2 * INV9;
        float entropy  = -sl * INV9;

        float sa = 0.0f;
        #pragma unroll
        for (int r = 0; r < 3; r++) {
            #pragma unroll
            for (int c = 0; c < 3; c++)
                sa += fabsf(p[r][j + c] - m);
        }
        float hom = __fdividef(1.0f, fmaf(sa, INV9, 1.0f));

        oc[j] = (contrast + EPS) * ENH;
        oe[j] = (energy   + EPS) * ENH;
        on[j] = (entropy  + EPS) * ENH;
        oh[j] = (hom      + EPS) * ENH;
    }

    // ---- Coalesced float4 stores: 4 feature planes at img*4 + f ----
    const size_t plane = (size_t)IMG_H * IMG_W;
    float* ob = out + (size_t)img * 4 * plane + (size_t)(y0 + ty) * IMG_W + x0 + cx;

    *reinterpret_cast<float4*>(ob + 0 * plane) = make_float4(oc[0], oc[1], oc[2], oc[3]);
    *reinterpret_cast<float4*>(ob + 1 * plane) = make_float4(oe[0], oe[1], oe[2], oe[3]);
    *reinterpret_cast<float4*>(ob + 2 * plane) = make_float4(on[0], on[1], on[2], on[3]);
    *reinterpret_cast<float4*>(ob + 3 * plane) = make_float4(oh[0], oh[1], oh[2], oh[3]);
}

extern "C" void kernel_launch(void* const* d_in, const int* in_sizes, int n_in,
                              void* d_out, int out_size)
{
    const float* x = (const float*)d_in[0];
    float* out = (float*)d_out;

    dim3 grid(IMG_W / TW, IMG_H / TH, 8 * 16);  // (4, 16, 128)
    dim3 block(256);
    texture_martingale_kernel<<<grid, block>>>(x, out);
}

// round 9
// speedup vs baseline: 1.1617x; 1.1617x over previous
#include <cuda_runtime.h>
#include <cuda_bf16.h>

// TextureMartingaleModule: x[8,16,256,256] f32 -> out[8,64,256,256] f32
// Per channel, per pixel (3x3 zero-padded window):
//   contrast = (S2c/9) / (sqrt(S2c/8)+eps)^2,  S2c = sum(p^2) - s1^2/9
//   energy   = sum(p^2)/9
//   entropy  = -sum(p*log(p+eps))/9
//   homog    = 1 / (1 + sum|p - mean|/9)
//   out      = (feat + eps) * exp(-0.5)        (theta=1 collapses exp/log)
//
// R6 -> R7: issue/LDS-bound (L1 56.6%, issue 69.8%, DRAM only 32%).
//   - vector LDS (stride 68, 16B-aligned rows): 6-wide row read = LDS.128+LDS.64
//   - 2 output rows per thread (tile 64x32): 4 halo rows feed 2 windows,
//     LDS per output drops 4.5 -> 2, column sums shared across windows.

#define IMG_H 256
#define IMG_W 256
#define TW 64           // tile width (outputs)
#define TH 32           // tile height (outputs)
#define SROWS (TH + 2)  // 34
#define SSTRIDE 68      // 68*4 = 272 bytes: 16B-aligned rows for float4 LDS

__global__ __launch_bounds__(256, 3)
void texture_martingale_kernel(const float* __restrict__ x,
                               float* __restrict__ out)
{
    __shared__ __align__(16) float sp[SROWS][SSTRIDE];
    __shared__ __align__(16) float sq[SROWS][SSTRIDE];

    const int img = blockIdx.z;                  // b*C + c  (0..127)
    const int x0  = blockIdx.x * TW;
    const int y0  = blockIdx.y * TH;
    const float* __restrict__ base = x + (size_t)img * (IMG_H * IMG_W);

    const int tid = threadIdx.x;

    // ---- Fill halo tile: p and q = p*log(p+eps), zero padding outside ----
    #pragma unroll
    for (int i = tid; i < SROWS * SSTRIDE; i += 256) {
        int r = i / SSTRIDE;
        int c = i - r * SSTRIDE;
        int gy = y0 + r - 1;
        int gx = x0 + c - 1;
        float p = 0.0f;
        if ((unsigned)gy < (unsigned)IMG_H && (unsigned)gx < (unsigned)IMG_W)
            p = __ldg(base + gy * IMG_W + gx);
        sp[r][c] = p;
        sq[r][c] = p * __logf(p + 1e-6f);
    }
    __syncthreads();

    // ---- Each thread: 4 x-consecutive outputs in 2 consecutive rows ----
    const int tx = tid & 15;          // 0..15 -> x quad
    const int ty = tid >> 4;          // 0..15 -> row pair
    const int cx = tx * 4;            // smem col base (taps span cx..cx+5)
    const int ry = ty * 2;            // smem halo row base (rows ry..ry+3)

    float pv[4][6];
    float c1w[2][6], c2w[2][6], cqw[2][6];
    #pragma unroll
    for (int c = 0; c < 6; c++) {
        c1w[0][c] = c1w[1][c] = 0.f;
        c2w[0][c] = c2w[1][c] = 0.f;
        cqw[0][c] = cqw[1][c] = 0.f;
    }

    #pragma unroll
    for (int r = 0; r < 4; r++) {
        const float4 a4 = *reinterpret_cast<const float4*>(&sp[ry + r][cx]);
        const float2 a2 = *reinterpret_cast<const float2*>(&sp[ry + r][cx + 4]);
        const float4 b4 = *reinterpret_cast<const float4*>(&sq[ry + r][cx]);
        const float2 b2 = *reinterpret_cast<const float2*>(&sq[ry + r][cx + 4]);
        float pr[6] = {a4.x, a4.y, a4.z, a4.w, a2.x, a2.y};
        float qr[6] = {b4.x, b4.y, b4.z, b4.w, b2.x, b2.y};

        #pragma unroll
        for (int c = 0; c < 6; c++) {
            pv[r][c] = pr[c];
            float s = pr[c] * pr[c];
            if (r < 3) {                       // window 0: rows 0..2
                c1w[0][c] += pr[c];
                c2w[0][c] += s;
                cqw[0][c] += qr[c];
            }
            if (r > 0) {                       // window 1: rows 1..3
                c1w[1][c] += pr[c];
                c2w[1][c] += s;
                cqw[1][c] += qr[c];
            }
        }
    }

    const float INV9 = 1.0f / 9.0f;
    const float ENH  = 0.60653065971263342f;  // exp(-0.5)
    const float EPS  = 1e-6f;
    const size_t plane = (size_t)IMG_H * IMG_W;

    #pragma unroll
    for (int w = 0; w < 2; w++) {
        float oc[4], oe[4], on[4], oh[4];

        #pragma unroll
        for (int j = 0; j < 4; j++) {
            float s1 = c1w[w][j] + c1w[w][j + 1] + c1w[w][j + 2];
            float s2 = c2w[w][j] + c2w[w][j + 1] + c2w[w][j + 2];
            float sl = cqw[w][j] + cqw[w][j + 1] + cqw[w][j + 2];

            float m  = s1 * INV9;
            float v  = fmaxf(s2 - s1 * m, 0.0f);        // sum (p - m)^2
            float sd = sqrtf(v * 0.125f) + EPS;         // unbiased std + eps
            float contrast = __fdividef(v * INV9, sd * sd);
            float energy   = s2 * INV9;
            float entropy  = -sl * INV9;

            float sa = 0.0f;
            #pragma unroll
            for (int r = 0; r < 3; r++) {
                #pragma unroll
                for (int c = 0; c < 3; c++)
                    sa += fabsf(pv[w + r][j + c] - m);
            }
            float hom = __fdividef(1.0f, fmaf(sa, INV9, 1.0f));

            oc[j] = (contrast + EPS) * ENH;
            oe[j] = (energy   + EPS) * ENH;
            on[j] = (entropy  + EPS) * ENH;
            oh[j] = (hom      + EPS) * ENH;
        }

        float* ob = out + (size_t)img * 4 * plane
                        + (size_t)(y0 + ry + w) * IMG_W + x0 + cx;

        *reinterpret_cast<float4*>(ob + 0 * plane) = make_float4(oc[0], oc[1], oc[2], oc[3]);
        *reinterpret_cast<float4*>(ob + 1 * plane) = make_float4(oe[0], oe[1], oe[2], oe[3]);
        *reinterpret_cast<float4*>(ob + 2 * plane) = make_float4(on[0], on[1], on[2], on[3]);
        *reinterpret_cast<float4*>(ob + 3 * plane) = make_float4(oh[0], oh[1], oh[2], oh[3]);
    }
}

extern "C" void kernel_launch(void* const* d_in, const int* in_sizes, int n_in,
                              void* d_out, int out_size)
{
    const float* x = (const float*)d_in[0];
    float* out = (float*)d_out;

    dim3 grid(IMG_W / TW, IMG_H / TH, 8 * 16);  // (4, 8, 128)
    dim3 block(256);
    texture_martingale_kernel<<<grid, block>>>(x, out);
}